// round 1
// baseline (speedup 1.0000x reference)
#include <cuda_runtime.h>
#include <cuda_bf16.h>

#define NB 2
#define NH 8
#define SEQ 4096
#define DK 128
#define DV 128
#define CHK 32
#define NCHUNK 128                 // chunks per (b,h)
#define BHN (NB*NH)                // 16
#define TOTAL_CHUNKS (BHN*NCHUNK)  // 2048
#define O_ELEMS (NB*NH*SEQ*DV)     // 8388608
#define S_ELEMS (NB*NH*DK*DV)      // 262144

// ---- scratch (static device arrays; no runtime allocation) ----
__device__ float g_qT  [(size_t)TOTAL_CHUNKS*CHK*DK];  // per chunk: [d][i] transposed
__device__ float g_k   [(size_t)TOTAL_CHUNKS*CHK*DK];  // per chunk: [i][d]
__device__ float g_u   [(size_t)TOTAL_CHUNKS*CHK*DV];  // per chunk: [i][j]
__device__ float g_wT  [(size_t)TOTAL_CHUNKS*CHK*DK];  // per chunk: [d][i] transposed
__device__ float g_attT[(size_t)TOTAL_CHUNKS*CHK*CHK]; // per chunk: [t][i] transposed tril(q k^T)

// ============================================================================
// Kernel 1: fully parallel per-chunk preprocessing (2048 CTAs x 256 threads)
// ============================================================================
__global__ __launch_bounds__(256) void prep_kernel(
    const float* __restrict__ q, const float* __restrict__ k,
    const float* __restrict__ v, const float* __restrict__ beta)
{
    extern __shared__ float sm[];
    float* qs    = sm;            // 4096 (normalized q)
    float* ks    = qs + 4096;     // 4096 (normalized k)
    float* vs    = ks + 4096;     // 4096 (v * beta)
    float* A     = vs + 4096;     // 1024
    float* betas = A + 1024;      // 32
    float* rinv  = betas + 32;    // 64 (rq[32], rk[32])

    const int tid = threadIdx.x;
    const int chunk = blockIdx.x;
    const size_t base = (size_t)chunk * (CHK*DK);

    // --- load q,k,v tile (float4) + beta ---
    {
        const float4* q4 = (const float4*)(q + base);
        const float4* k4 = (const float4*)(k + base);
        const float4* v4 = (const float4*)(v + base);
        float4* qs4=(float4*)qs; float4* ks4=(float4*)ks; float4* vs4=(float4*)vs;
        for (int e = tid; e < 1024; e += 256) { qs4[e]=q4[e]; ks4[e]=k4[e]; vs4[e]=v4[e]; }
        if (tid < CHK) betas[tid] = beta[(size_t)chunk*CHK + tid];
    }
    __syncthreads();

    // --- row l2-norm factors ---
    if (tid < 64) {
        int r = tid & 31;
        const float* src = (tid < 32) ? (qs + r*DK) : (ks + r*DK);
        float s = 0.f;
        #pragma unroll 8
        for (int d = 0; d < DK; d++) { float x = src[d]; s += x*x; }
        rinv[tid] = rsqrtf(s + 1e-6f);
    }
    __syncthreads();

    // --- scale: qn, kn, v*beta ---
    for (int e = tid; e < 4096; e += 256) {
        int r = e >> 7;
        qs[e] *= rinv[r];
        ks[e] *= rinv[32 + r];
        vs[e] *= betas[r];
    }
    __syncthreads();

    // --- A[i][j] = -(beta_i * kn_i . kn_j) for j<i, else 0 ---
    for (int o = tid; o < 1024; o += 256) {
        int i = o >> 5, j = o & 31;
        float val = 0.f;
        if (j < i) {
            const float4* a4 = (const float4*)(ks + i*DK);
            const float4* b4 = (const float4*)(ks + j*DK);
            float s = 0.f;
            #pragma unroll 8
            for (int m = 0; m < 32; m++) {
                float4 a = a4[m], b = b4[m];
                s += a.x*b.x + a.y*b.y + a.z*b.z + a.w*b.w;
            }
            val = -betas[i] * s;
        }
        A[o] = val;
    }
    __syncthreads();

    // --- forward substitution: invert (I - A), strictly-lower A (warp 0) ---
    if (tid < 32) {
        for (int i = 1; i < CHK; i++) {
            float upd = 0.f;
            if (tid < i) {
                for (int j = 0; j < i; j++) upd += A[i*CHK + j] * A[j*CHK + tid];
            }
            __syncwarp();
            if (tid < i) A[i*CHK + tid] += upd;
            __syncwarp();
        }
    }
    __syncthreads();

    // --- add I, round-trip through bf16 (matches reference .astype(bf16)) ---
    for (int o = tid; o < 1024; o += 256) {
        int i = o >> 5, j = o & 31;
        float val = A[o] + ((i == j) ? 1.f : 0.f);
        A[o] = __bfloat162float(__float2bfloat16(val));
    }
    __syncthreads();

    // --- u = A @ (v*beta), w = A @ (beta*kn) [store w transposed] ---
    {
        int i  = tid >> 3;
        int cb = (tid & 7) * 16;
        float ua[16], wa[16];
        #pragma unroll
        for (int m = 0; m < 16; m++) { ua[m] = 0.f; wa[m] = 0.f; }
        for (int t = 0; t < CHK; t++) {
            float a  = A[i*CHK + t];
            float ab = a * betas[t];
            const float* vr = vs + t*DV + cb;
            const float* kr = ks + t*DK + cb;
            #pragma unroll
            for (int m = 0; m < 16; m++) { ua[m] += a*vr[m]; wa[m] += ab*kr[m]; }
        }
        float* up = g_u + (size_t)chunk*(CHK*DV) + i*DV + cb;
        #pragma unroll
        for (int m = 0; m < 16; m += 4)
            *(float4*)(up + m) = make_float4(ua[m], ua[m+1], ua[m+2], ua[m+3]);
        float* wtp = g_wT + (size_t)chunk*(CHK*DK);
        #pragma unroll
        for (int m = 0; m < 16; m++) wtp[(cb + m)*CHK + i] = wa[m];
    }

    // --- att_local = tril(qn @ kn^T) incl diag, stored transposed [t][i] ---
    for (int o = tid; o < 1024; o += 256) {
        int i = o >> 5, j = o & 31;
        float val = 0.f;
        if (j <= i) {
            const float4* a4 = (const float4*)(qs + i*DK);
            const float4* b4 = (const float4*)(ks + j*DK);
            float s = 0.f;
            #pragma unroll 8
            for (int m = 0; m < 32; m++) {
                float4 a = a4[m], b = b4[m];
                s += a.x*b.x + a.y*b.y + a.z*b.z + a.w*b.w;
            }
            val = s;
        }
        g_attT[(size_t)chunk*(CHK*CHK) + j*CHK + i] = val;
    }

    // --- copies: qn transposed, kn natural ---
    for (int e = tid; e < 4096; e += 256) {
        int i = e >> 7, d = e & 127;
        g_qT[(size_t)chunk*(CHK*DK) + d*CHK + i] = qs[e];
    }
    {
        float4* kp = (float4*)(g_k + (size_t)chunk*(CHK*DK));
        const float4* ks4 = (const float4*)ks;
        for (int e = tid; e < 1024; e += 256) kp[e] = ks4[e];
    }
}

// ============================================================================
// Kernel 2: serial scan over chunks. 64 CTAs = 16 (b,h) x 4 column blocks.
// Each CTA carries S slice [128 x 32] in smem.
// ============================================================================
__global__ __launch_bounds__(256) void scan_kernel(float* __restrict__ out, int write_state)
{
    extern __shared__ float sm[];
    float* S    = sm;            // 128*32
    float* wT   = S + 4096;      // 128*32  [d][i]
    float* qT   = wT + 4096;     // 128*32  [d][i]
    float* ks   = qT + 4096;     // 32*128  [i][d]
    float* un   = ks + 4096;     // 32*32   u -> u_new (in place)
    float* attT = un + 1024;     // 32*32   [t][i]

    const int tid = threadIdx.x;
    const int bh = blockIdx.x >> 2;
    const int j0 = (blockIdx.x & 3) * 32;

    for (int e = tid; e < 4096; e += 256) S[e] = 0.f;
    __syncthreads();

    const int rg = tid >> 4;   // 0..15 : rows {2rg, 2rg+1}
    const int cg = tid & 15;   // 0..15 : cols {2cg, 2cg+1}
    const int dg = tid >> 3;   // 0..31 : d rows {4dg..4dg+3}
    const int jg = tid & 7;    // 0..7  : cols {4jg..4jg+3}

    for (int t = 0; t < NCHUNK; t++) {
        const size_t chunk = (size_t)bh*NCHUNK + t;

        // ---- stage chunk data into smem ----
        {
            const float4* wg = (const float4*)(g_wT + chunk*(CHK*DK));
            const float4* qg = (const float4*)(g_qT + chunk*(CHK*DK));
            const float4* kg = (const float4*)(g_k  + chunk*(CHK*DK));
            float4* w4 = (float4*)wT; float4* q4 = (float4*)qT; float4* k4 = (float4*)ks;
            for (int e = tid; e < 1024; e += 256) { w4[e]=wg[e]; q4[e]=qg[e]; k4[e]=kg[e]; }
            {   // u slice [32 x 32] of g_u
                int e = tid * 4;
                int i = e >> 5, c = e & 31;
                *(float4*)(un + e) = *(const float4*)(g_u + chunk*(CHK*DV) + i*DV + j0 + c);
            }
            ((float4*)attT)[tid & 255] = ((const float4*)(g_attT + chunk*(CHK*CHK)))[tid];
        }
        __syncthreads();

        // ---- Pass A: u_new = u - w @ S (2x2 register tile) ----
        {
            const int r0 = rg*2, c0 = cg*2;
            float a00 = un[r0*32 + c0],       a01 = un[r0*32 + c0 + 1];
            float a10 = un[(r0+1)*32 + c0],   a11 = un[(r0+1)*32 + c0 + 1];
            #pragma unroll 4
            for (int d = 0; d < DK; d++) {
                float2 wv = *(const float2*)(wT + d*32 + r0);
                float2 sv = *(const float2*)(S  + d*32 + c0);
                a00 -= wv.x*sv.x; a01 -= wv.x*sv.y;
                a10 -= wv.y*sv.x; a11 -= wv.y*sv.y;
            }
            __syncthreads();
            un[r0*32 + c0]     = a00; un[r0*32 + c0 + 1]     = a01;
            un[(r0+1)*32 + c0] = a10; un[(r0+1)*32 + c0 + 1] = a11;
            __syncthreads();
        }

        // ---- Pass B: o = q @ S + att_local @ u_new ; write to global ----
        {
            const int r0 = rg*2, c0 = cg*2;
            float o00=0.f, o01=0.f, o10=0.f, o11=0.f;
            #pragma unroll 4
            for (int d = 0; d < DK; d++) {
                float2 qv = *(const float2*)(qT + d*32 + r0);
                float2 sv = *(const float2*)(S  + d*32 + c0);
                o00 += qv.x*sv.x; o01 += qv.x*sv.y;
                o10 += qv.y*sv.x; o11 += qv.y*sv.y;
            }
            #pragma unroll 4
            for (int u2 = 0; u2 < CHK; u2++) {
                float2 av = *(const float2*)(attT + u2*32 + r0);
                float2 uv = *(const float2*)(un   + u2*32 + c0);
                o00 += av.x*uv.x; o01 += av.x*uv.y;
                o10 += av.y*uv.x; o11 += av.y*uv.y;
            }
            const size_t lbase = (size_t)bh*SEQ + (size_t)t*CHK;
            float* op0 = out + (lbase + r0    )*DV + j0 + c0;
            float* op1 = out + (lbase + r0 + 1)*DV + j0 + c0;
            *(float2*)op0 = make_float2(o00, o01);
            *(float2*)op1 = make_float2(o10, o11);
            __syncthreads();   // all S reads done before pass C mutates S
        }

        // ---- Pass C: S += k^T @ u_new (4x4 register tile) ----
        {
            const int d0 = dg*4, c0 = jg*4;
            float acc[4][4];
            #pragma unroll
            for (int r = 0; r < 4; r++) {
                float4 s = *(const float4*)(S + (d0+r)*32 + c0);
                acc[r][0]=s.x; acc[r][1]=s.y; acc[r][2]=s.z; acc[r][3]=s.w;
            }
            #pragma unroll 4
            for (int i = 0; i < CHK; i++) {
                float4 kv = *(const float4*)(ks + i*DK + d0);
                float4 uv = *(const float4*)(un + i*32 + c0);
                acc[0][0]+=kv.x*uv.x; acc[0][1]+=kv.x*uv.y; acc[0][2]+=kv.x*uv.z; acc[0][3]+=kv.x*uv.w;
                acc[1][0]+=kv.y*uv.x; acc[1][1]+=kv.y*uv.y; acc[1][2]+=kv.y*uv.z; acc[1][3]+=kv.y*uv.w;
                acc[2][0]+=kv.z*uv.x; acc[2][1]+=kv.z*uv.y; acc[2][2]+=kv.z*uv.z; acc[2][3]+=kv.z*uv.w;
                acc[3][0]+=kv.w*uv.x; acc[3][1]+=kv.w*uv.y; acc[3][2]+=kv.w*uv.z; acc[3][3]+=kv.w*uv.w;
            }
            #pragma unroll
            for (int r = 0; r < 4; r++)
                *(float4*)(S + (d0+r)*32 + c0) =
                    make_float4(acc[r][0], acc[r][1], acc[r][2], acc[r][3]);
            __syncthreads();
        }
    }

    // ---- optional final-state output (reference returns (o, S)) ----
    if (write_state) {
        #pragma unroll
        for (int m = 0; m < 4; m++) {
            int e = tid*16 + m*4;
            int d = e >> 5, c = e & 31;
            *(float4*)(out + (size_t)O_ELEMS + (size_t)bh*(DK*DV) + d*DV + j0 + c) =
                *(const float4*)(S + e);
        }
    }
}

// ============================================================================
extern "C" void kernel_launch(void* const* d_in, const int* in_sizes, int n_in,
                              void* d_out, int out_size) {
    const float* q    = (const float*)d_in[0];
    const float* k    = (const float*)d_in[1];
    const float* v    = (const float*)d_in[2];
    const float* beta = (const float*)d_in[3];
    float* out = (float*)d_out;

    const int smem1 = (4096*3 + 1024 + 32 + 64) * 4;          // 53632 B
    const int smem2 = (4096*4 + 1024 + 1024) * 4;             // 73728 B
    cudaFuncSetAttribute(prep_kernel, cudaFuncAttributeMaxDynamicSharedMemorySize, smem1);
    cudaFuncSetAttribute(scan_kernel, cudaFuncAttributeMaxDynamicSharedMemorySize, smem2);

    const int write_state = (out_size >= O_ELEMS + S_ELEMS) ? 1 : 0;

    prep_kernel<<<TOTAL_CHUNKS, 256, smem1>>>(q, k, v, beta);
    scan_kernel<<<BHN*4, 256, smem2>>>(out, write_state);
}

// round 2
// speedup vs baseline: 1.3007x; 1.3007x over previous
#include <cuda_runtime.h>
#include <cuda_bf16.h>
#include <cstdint>

#define NB 2
#define NH 8
#define SEQ 4096
#define DK 128
#define DV 128
#define CHK 32
#define NCHUNK 128                 // chunks per (b,h)
#define BHN (NB*NH)                // 16
#define TOTAL_CHUNKS (BHN*NCHUNK)  // 2048
#define O_ELEMS (NB*NH*SEQ*DV)     // 8388608
#define S_ELEMS (NB*NH*DK*DV)      // 262144

// ---- scratch (static device arrays; no runtime allocation) ----
// Duplicated-broadcast layouts for f32x2 FMA:
//  g_w4[chunk][dd][i][4] = {-w(i,2dd),-w(i,2dd),-w(i,2dd+1),-w(i,2dd+1)}   (dd=0..63)
//  g_q4[chunk][dd][i][4] = { q(i,2dd), q(i,2dd), q(i,2dd+1), q(i,2dd+1)}
//  g_k4[chunk][i][dp][4] = { k(i,2dp), k(i,2dp), k(i,2dp+1), k(i,2dp+1)}   (dp=0..63)
//  g_a4[chunk][tt][i][4] = {att(i,2tt),att(i,2tt),att(i,2tt+1),att(i,2tt+1)} (tt=0..15)
//  g_u [chunk][i][j]     = (T @ v*beta)(i,j), j=0..127
__device__ float g_w4[(size_t)TOTAL_CHUNKS*8192];
__device__ float g_q4[(size_t)TOTAL_CHUNKS*8192];
__device__ float g_k4[(size_t)TOTAL_CHUNKS*8192];
__device__ float g_a4[(size_t)TOTAL_CHUNKS*2048];
__device__ float g_u [(size_t)TOTAL_CHUNKS*4096];

typedef unsigned long long u64t;

__device__ __forceinline__ void ffma2(u64t& d, u64t a, u64t b) {
    asm("fma.rn.f32x2 %0, %1, %2, %0;" : "+l"(d) : "l"(a), "l"(b));
}
__device__ __forceinline__ void cpa16(uint32_t s, const void* g) {
    asm volatile("cp.async.cg.shared.global [%0], [%1], 16;" :: "r"(s), "l"(g));
}
__device__ __forceinline__ void cpa_commit() { asm volatile("cp.async.commit_group;"); }
__device__ __forceinline__ void cpa_wait0()  { asm volatile("cp.async.wait_group 0;" ::: "memory"); }

// ============================================================================
// Kernel 1: fully parallel per-chunk preprocessing (2048 CTAs x 256 threads)
// ============================================================================
__global__ __launch_bounds__(256) void prep_kernel(
    const float* __restrict__ q, const float* __restrict__ k,
    const float* __restrict__ v, const float* __restrict__ beta)
{
    extern __shared__ float sm[];
    float* qs    = sm;            // 4096 (normalized q)
    float* ks    = qs + 4096;     // 4096 (normalized k)
    float* vs    = ks + 4096;     // 4096 (v * beta), later reused as attS (1024)
    float* A     = vs + 4096;     // 1024
    float* betas = A + 1024;      // 32
    float* rinv  = betas + 32;    // 64 (rq[32], rk[32])

    const int tid = threadIdx.x;
    const int chunk = blockIdx.x;
    const size_t base = (size_t)chunk * (CHK*DK);

    // --- load q,k,v tile (float4) + beta ---
    {
        const float4* q4p = (const float4*)(q + base);
        const float4* k4p = (const float4*)(k + base);
        const float4* v4p = (const float4*)(v + base);
        float4* qs4=(float4*)qs; float4* ks4=(float4*)ks; float4* vs4=(float4*)vs;
        for (int e = tid; e < 1024; e += 256) { qs4[e]=q4p[e]; ks4[e]=k4p[e]; vs4[e]=v4p[e]; }
        if (tid < CHK) betas[tid] = beta[(size_t)chunk*CHK + tid];
    }
    __syncthreads();

    // --- row l2-norm factors ---
    if (tid < 64) {
        int r = tid & 31;
        const float* src = (tid < 32) ? (qs + r*DK) : (ks + r*DK);
        float s = 0.f;
        #pragma unroll 8
        for (int d = 0; d < DK; d++) { float x = src[d]; s += x*x; }
        rinv[tid] = rsqrtf(s + 1e-6f);
    }
    __syncthreads();

    // --- scale: qn, kn, v*beta ---
    for (int e = tid; e < 4096; e += 256) {
        int r = e >> 7;
        qs[e] *= rinv[r];
        ks[e] *= rinv[32 + r];
        vs[e] *= betas[r];
    }
    __syncthreads();

    // --- A[i][j] = -(beta_i * kn_i . kn_j) for j<i, else 0 ---
    for (int o = tid; o < 1024; o += 256) {
        int i = o >> 5, j = o & 31;
        float val = 0.f;
        if (j < i) {
            const float4* a4 = (const float4*)(ks + i*DK);
            const float4* b4 = (const float4*)(ks + j*DK);
            float s = 0.f;
            #pragma unroll 8
            for (int m = 0; m < 32; m++) {
                float4 a = a4[m], b = b4[m];
                s += a.x*b.x + a.y*b.y + a.z*b.z + a.w*b.w;
            }
            val = -betas[i] * s;
        }
        A[o] = val;
    }
    __syncthreads();

    // --- forward substitution: invert (I - A), strictly-lower A (warp 0) ---
    if (tid < 32) {
        for (int i = 1; i < CHK; i++) {
            float upd = 0.f;
            if (tid < i) {
                for (int j = 0; j < i; j++) upd += A[i*CHK + j] * A[j*CHK + tid];
            }
            __syncwarp();
            if (tid < i) A[i*CHK + tid] += upd;
            __syncwarp();
        }
    }
    __syncthreads();

    // --- add I, round-trip through bf16 (matches reference .astype(bf16)) ---
    for (int o = tid; o < 1024; o += 256) {
        int i = o >> 5, j = o & 31;
        float val = A[o] + ((i == j) ? 1.f : 0.f);
        A[o] = __bfloat162float(__float2bfloat16(val));
    }
    __syncthreads();

    // --- u = A @ (v*beta) -> g_u ; w = A @ (beta*kn) -> g_w4 (negated, dup) ---
    {
        int i  = tid >> 3;
        int cb = (tid & 7) * 16;
        float ua[16], wa[16];
        #pragma unroll
        for (int m = 0; m < 16; m++) { ua[m] = 0.f; wa[m] = 0.f; }
        for (int t = 0; t < CHK; t++) {
            float a  = A[i*CHK + t];
            float ab = a * betas[t];
            const float* vr = vs + t*DV + cb;
            const float* kr = ks + t*DK + cb;
            #pragma unroll
            for (int m = 0; m < 16; m++) { ua[m] += a*vr[m]; wa[m] += ab*kr[m]; }
        }
        float* up = g_u + (size_t)chunk*4096 + i*DV + cb;
        #pragma unroll
        for (int m = 0; m < 16; m += 4)
            *(float4*)(up + m) = make_float4(ua[m], ua[m+1], ua[m+2], ua[m+3]);
        float* wp = g_w4 + (size_t)chunk*8192;
        #pragma unroll
        for (int m = 0; m < 16; m += 2) {
            int dd = (cb + m) >> 1;
            *(float4*)(wp + dd*128 + i*4) =
                make_float4(-wa[m], -wa[m], -wa[m+1], -wa[m+1]);
        }
    }

    // --- q4 dup layout ---
    for (int idx = tid; idx < 2048; idx += 256) {
        int dd = idx >> 5, i = idx & 31;
        float a = qs[i*DK + 2*dd], b = qs[i*DK + 2*dd + 1];
        *(float4*)(g_q4 + (size_t)chunk*8192 + dd*128 + i*4) = make_float4(a, a, b, b);
    }
    // --- k4 dup layout ---
    for (int idx = tid; idx < 2048; idx += 256) {
        int i = idx >> 6, dp = idx & 63;
        float a = ks[i*DK + 2*dp], b = ks[i*DK + 2*dp + 1];
        *(float4*)(g_k4 + (size_t)chunk*8192 + i*256 + dp*4) = make_float4(a, a, b, b);
    }

    // --- att_local = tril(qn @ kn^T) incl diag -> attS (reuse vs), then dup out ---
    __syncthreads();   // all reads of vs (u compute) done
    float* attS = vs;  // 1024 floats
    for (int o = tid; o < 1024; o += 256) {
        int i = o >> 5, j = o & 31;
        float val = 0.f;
        if (j <= i) {
            const float4* a4 = (const float4*)(qs + i*DK);
            const float4* b4 = (const float4*)(ks + j*DK);
            float s = 0.f;
            #pragma unroll 8
            for (int m = 0; m < 32; m++) {
                float4 a = a4[m], b = b4[m];
                s += a.x*b.x + a.y*b.y + a.z*b.z + a.w*b.w;
            }
            val = s;
        }
        attS[o] = val;
    }
    __syncthreads();
    for (int idx = tid; idx < 512; idx += 256) {
        int tt = idx >> 5, i = idx & 31;
        float a = attS[i*32 + 2*tt], b = attS[i*32 + 2*tt + 1];
        *(float4*)(g_a4 + (size_t)chunk*2048 + tt*128 + i*4) = make_float4(a, a, b, b);
    }
}

// ============================================================================
// Kernel 2: serial scan. 64 CTAs = 16 (b,h) x 4 column blocks (32 cols each).
// S slice [128 x 32] lives in smem. f32x2 FMA + cp.async double-buffered stage.
// ============================================================================

// smem float offsets
#define SM_S    0
#define SM_W4   4096
#define SM_Q4   12288
#define SM_K4   20480   // 2 x 8192
#define SM_A4   36864   // 2 x 2048
#define SM_UST  40960   // 2 x 1024
#define SM_UN   43008   // 1024
#define SM_TOT  44032

__global__ __launch_bounds__(256, 1) void scan_kernel(float* __restrict__ out, int write_state)
{
    extern __shared__ float sm[];
    float* S  = sm + SM_S;
    float* W4 = sm + SM_W4;
    float* Q4 = sm + SM_Q4;
    float* K4 = sm + SM_K4;
    float* A4 = sm + SM_A4;
    float* UST= sm + SM_UST;
    float* UN = sm + SM_UN;

    const int tid = threadIdx.x;
    const int bh = blockIdx.x >> 2;
    const int j0 = (blockIdx.x & 3) * 32;

    for (int e = tid; e < 4096; e += 256) S[e] = 0.f;

    // pass-1 / o mapping: row i1, cols c1..c1+3
    const int i1 = tid >> 3;
    const int c1 = (tid & 7) * 4;
    // pass-2 S-update mapping: rows 2*dp, 2*dp+1, cols c2..c2+7
    const int dp = tid >> 2;
    const int c2 = (tid & 3) * 8;

    const size_t cbase = (size_t)bh * NCHUNK;

    // ---- initial stage (chunk 0 -> buffer 0) ----
    {
        const size_t ch = cbase;
        uint32_t sw = (uint32_t)__cvta_generic_to_shared(W4);
        uint32_t sq = (uint32_t)__cvta_generic_to_shared(Q4);
        uint32_t sk = (uint32_t)__cvta_generic_to_shared(K4);
        uint32_t sa = (uint32_t)__cvta_generic_to_shared(A4);
        uint32_t su = (uint32_t)__cvta_generic_to_shared(UST);
        const float4* gw = (const float4*)(g_w4 + ch*8192);
        const float4* gq = (const float4*)(g_q4 + ch*8192);
        const float4* gk = (const float4*)(g_k4 + ch*8192);
        const float4* ga = (const float4*)(g_a4 + ch*2048);
        for (int e = tid; e < 2048; e += 256) {
            cpa16(sw + e*16, gw + e);
            cpa16(sq + e*16, gq + e);
            cpa16(sk + e*16, gk + e);
        }
        for (int e = tid; e < 512; e += 256) cpa16(sa + e*16, ga + e);
        cpa16(su + tid*16, g_u + ch*4096 + (tid>>3)*DV + j0 + (tid&7)*4);
        cpa_commit();
        cpa_wait0();
    }
    __syncthreads();

    for (int t = 0; t < NCHUNK; t++) {
        const int buf = t & 1;
        const int nbuf = buf ^ 1;
        const float* K4b = K4 + buf*8192;
        const float* A4b = A4 + buf*2048;
        const float* USTb = UST + buf*1024;

        // ---- Pass 1 (fused): u_new = u - w@S ; o_part = q@S ----
        u64t u0, u1, o0 = 0ull, o1 = 0ull;
        {
            const ulonglong2 uu = *(const ulonglong2*)(USTb + i1*32 + c1);
            u0 = uu.x; u1 = uu.y;
        }
        #pragma unroll 8
        for (int dd = 0; dd < 64; dd++) {
            const ulonglong2 wv = *(const ulonglong2*)(W4 + dd*128 + i1*4);
            const ulonglong2 qv = *(const ulonglong2*)(Q4 + dd*128 + i1*4);
            const ulonglong2 s0 = *(const ulonglong2*)(S + (2*dd  )*32 + c1);
            const ulonglong2 s1 = *(const ulonglong2*)(S + (2*dd+1)*32 + c1);
            ffma2(u0, wv.x, s0.x); ffma2(u1, wv.x, s0.y);
            ffma2(u0, wv.y, s1.x); ffma2(u1, wv.y, s1.y);
            ffma2(o0, qv.x, s0.x); ffma2(o1, qv.x, s0.y);
            ffma2(o0, qv.y, s1.x); ffma2(o1, qv.y, s1.y);
        }
        {
            ulonglong2 w2; w2.x = u0; w2.y = u1;
            *(ulonglong2*)(UN + i1*32 + c1) = w2;
        }
        __syncthreads();   // UN visible; W4/Q4/UST[buf] free for prefetch

        // ---- prefetch chunk t+1 (overlaps pass 2) ----
        {
            const size_t ch = cbase + ((t+1 < NCHUNK) ? (t+1) : t);
            uint32_t sw = (uint32_t)__cvta_generic_to_shared(W4);
            uint32_t sq = (uint32_t)__cvta_generic_to_shared(Q4);
            uint32_t sk = (uint32_t)__cvta_generic_to_shared(K4 + nbuf*8192);
            uint32_t sa = (uint32_t)__cvta_generic_to_shared(A4 + nbuf*2048);
            uint32_t su = (uint32_t)__cvta_generic_to_shared(UST + nbuf*1024);
            const float4* gw = (const float4*)(g_w4 + ch*8192);
            const float4* gq = (const float4*)(g_q4 + ch*8192);
            const float4* gk = (const float4*)(g_k4 + ch*8192);
            const float4* ga = (const float4*)(g_a4 + ch*2048);
            for (int e = tid; e < 2048; e += 256) {
                cpa16(sw + e*16, gw + e);
                cpa16(sq + e*16, gq + e);
                cpa16(sk + e*16, gk + e);
            }
            for (int e = tid; e < 512; e += 256) cpa16(sa + e*16, ga + e);
            cpa16(su + tid*16, g_u + ch*4096 + (tid>>3)*DV + j0 + (tid&7)*4);
            cpa_commit();
        }

        // ---- Pass 2a: o = o_part + att_local @ u_new ; write out ----
        #pragma unroll 4
        for (int tt = 0; tt < 16; tt++) {
            const ulonglong2 av = *(const ulonglong2*)(A4b + tt*128 + i1*4);
            const ulonglong2 n0 = *(const ulonglong2*)(UN + (2*tt  )*32 + c1);
            const ulonglong2 n1 = *(const ulonglong2*)(UN + (2*tt+1)*32 + c1);
            ffma2(o0, av.x, n0.x); ffma2(o1, av.x, n0.y);
            ffma2(o0, av.y, n1.x); ffma2(o1, av.y, n1.y);
        }
        {
            ulonglong2 w2; w2.x = o0; w2.y = o1;
            *(ulonglong2*)(out + ((size_t)bh*SEQ + (size_t)t*CHK + i1)*DV + j0 + c1) = w2;
        }

        // ---- Pass 2b: S += k^T @ u_new ----
        {
            u64t a00, a01, a02, a03, a10, a11, a12, a13;
            {
                ulonglong2 r0a = *(const ulonglong2*)(S + (2*dp  )*32 + c2);
                ulonglong2 r0b = *(const ulonglong2*)(S + (2*dp  )*32 + c2 + 4);
                ulonglong2 r1a = *(const ulonglong2*)(S + (2*dp+1)*32 + c2);
                ulonglong2 r1b = *(const ulonglong2*)(S + (2*dp+1)*32 + c2 + 4);
                a00 = r0a.x; a01 = r0a.y; a02 = r0b.x; a03 = r0b.y;
                a10 = r1a.x; a11 = r1a.y; a12 = r1b.x; a13 = r1b.y;
            }
            #pragma unroll 8
            for (int i = 0; i < CHK; i++) {
                const ulonglong2 kv = *(const ulonglong2*)(K4b + i*256 + dp*4);
                const ulonglong2 na = *(const ulonglong2*)(UN + i*32 + c2);
                const ulonglong2 nb = *(const ulonglong2*)(UN + i*32 + c2 + 4);
                ffma2(a00, kv.x, na.x); ffma2(a01, kv.x, na.y);
                ffma2(a02, kv.x, nb.x); ffma2(a03, kv.x, nb.y);
                ffma2(a10, kv.y, na.x); ffma2(a11, kv.y, na.y);
                ffma2(a12, kv.y, nb.x); ffma2(a13, kv.y, nb.y);
            }
            ulonglong2 w2;
            w2.x = a00; w2.y = a01; *(ulonglong2*)(S + (2*dp  )*32 + c2    ) = w2;
            w2.x = a02; w2.y = a03; *(ulonglong2*)(S + (2*dp  )*32 + c2 + 4) = w2;
            w2.x = a10; w2.y = a11; *(ulonglong2*)(S + (2*dp+1)*32 + c2    ) = w2;
            w2.x = a12; w2.y = a13; *(ulonglong2*)(S + (2*dp+1)*32 + c2 + 4) = w2;
        }

        cpa_wait0();
        __syncthreads();   // S updated + next chunk staged
    }

    // ---- optional final-state output (reference returns (o, S)) ----
    if (write_state) {
        #pragma unroll
        for (int m = 0; m < 4; m++) {
            int e = tid*16 + m*4;
            int d = e >> 5, c = e & 31;
            *(float4*)(out + (size_t)O_ELEMS + (size_t)bh*(DK*DV) + d*DV + j0 + c) =
                *(const float4*)(S + e);
        }
    }
}

// ============================================================================
extern "C" void kernel_launch(void* const* d_in, const int* in_sizes, int n_in,
                              void* d_out, int out_size) {
    const float* q    = (const float*)d_in[0];
    const float* k    = (const float*)d_in[1];
    const float* v    = (const float*)d_in[2];
    const float* beta = (const float*)d_in[3];
    float* out = (float*)d_out;

    const int smem1 = (4096*3 + 1024 + 32 + 64) * 4;   // 53632 B
    const int smem2 = SM_TOT * 4;                      // 176128 B
    cudaFuncSetAttribute(prep_kernel, cudaFuncAttributeMaxDynamicSharedMemorySize, smem1);
    cudaFuncSetAttribute(scan_kernel, cudaFuncAttributeMaxDynamicSharedMemorySize, smem2);

    const int write_state = (out_size >= O_ELEMS + S_ELEMS) ? 1 : 0;

    prep_kernel<<<TOTAL_CHUNKS, 256, smem1>>>(q, k, v, beta);
    scan_kernel<<<BHN*4, 256, smem2>>>(out, write_state);
}

// round 4
// speedup vs baseline: 1.5584x; 1.1981x over previous
#include <cuda_runtime.h>
#include <cuda_bf16.h>
#include <cstdint>

#define NB 2
#define NH 8
#define SEQ 4096
#define DK 128
#define DV 128
#define CHK 32
#define NCHUNK 128                 // chunks per (b,h)
#define BHN (NB*NH)                // 16
#define TOTAL_CHUNKS (BHN*NCHUNK)  // 2048
#define O_ELEMS (NB*NH*SEQ*DV)     // 8388608
#define S_ELEMS (NB*NH*DK*DV)      // 262144

// ---- scratch (static device arrays; no runtime allocation) ----
// Duplicated-broadcast layouts for f32x2 FMA:
//  g_w4[chunk][dd][i][4] = {-w(i,2dd),-w(i,2dd),-w(i,2dd+1),-w(i,2dd+1)}   (dd=0..63)
//  g_q4[chunk][dd][i][4] = { q(i,2dd), q(i,2dd), q(i,2dd+1), q(i,2dd+1)}
//  g_k4[chunk][i][dp][4] = { k(i,2dp), k(i,2dp), k(i,2dp+1), k(i,2dp+1)}   (dp=0..63)
//  g_a4[chunk][tt][i][4] = {att(i,2tt),att(i,2tt),att(i,2tt+1),att(i,2tt+1)} (tt=0..15)
//  g_u [chunk][i][j]     = (T @ v*beta)(i,j), j=0..127
__device__ float g_w4[(size_t)TOTAL_CHUNKS*8192];
__device__ float g_q4[(size_t)TOTAL_CHUNKS*8192];
__device__ float g_k4[(size_t)TOTAL_CHUNKS*8192];
__device__ float g_a4[(size_t)TOTAL_CHUNKS*2048];
__device__ float g_u [(size_t)TOTAL_CHUNKS*4096];

typedef unsigned long long u64t;

__device__ __forceinline__ void ffma2(u64t& d, u64t a, u64t b) {
    asm("fma.rn.f32x2 %0, %1, %2, %0;" : "+l"(d) : "l"(a), "l"(b));
}
__device__ __forceinline__ u64t addf2(u64t a, u64t b) {
    u64t d; asm("add.rn.f32x2 %0, %1, %2;" : "=l"(d) : "l"(a), "l"(b)); return d;
}
__device__ __forceinline__ void cpa16(uint32_t s, const void* g) {
    asm volatile("cp.async.cg.shared.global [%0], [%1], 16;" :: "r"(s), "l"(g));
}
__device__ __forceinline__ void cpa8(uint32_t s, const void* g) {
    asm volatile("cp.async.ca.shared.global [%0], [%1], 8;" :: "r"(s), "l"(g));
}
__device__ __forceinline__ void cpa_commit() { asm volatile("cp.async.commit_group;"); }
__device__ __forceinline__ void cpa_wait0()  { asm volatile("cp.async.wait_group 0;" ::: "memory"); }

// ============================================================================
// Kernel 1: per-chunk preprocessing (2048 CTAs x 256 threads).
// All global stores of dup layouts staged through smem -> fully coalesced.
// Staging strides are multiples of 4 floats (16B) for float4 alignment.
// ============================================================================
#define PW 132   // stage row stride (floats) for [64][128]-style tiles
#define PK 260   // stage row stride (floats) for [32][256]-style tile
#define P_STAGE (4096*3 + 1024 + 32 + 64)
#define P_TOT   (P_STAGE + 8448)

__global__ __launch_bounds__(256) void prep_kernel(
    const float* __restrict__ q, const float* __restrict__ k,
    const float* __restrict__ v, const float* __restrict__ beta)
{
    extern __shared__ float sm[];
    float* qs    = sm;            // 4096 (normalized q)
    float* ks    = qs + 4096;     // 4096 (normalized k)
    float* vs    = ks + 4096;     // 4096 (v * beta), later reused as att (1024)
    float* A     = vs + 4096;     // 1024
    float* betas = A + 1024;      // 32
    float* rinv  = betas + 32;    // 64
    float* stage = sm + P_STAGE;  // 8448 staging for dup layouts

    const int tid = threadIdx.x;
    const int chunk = blockIdx.x;
    const size_t base = (size_t)chunk * (CHK*DK);

    // --- load q,k,v tile (float4) + beta ---
    {
        const float4* q4p = (const float4*)(q + base);
        const float4* k4p = (const float4*)(k + base);
        const float4* v4p = (const float4*)(v + base);
        float4* qs4=(float4*)qs; float4* ks4=(float4*)ks; float4* vs4=(float4*)vs;
        for (int e = tid; e < 1024; e += 256) { qs4[e]=q4p[e]; ks4[e]=k4p[e]; vs4[e]=v4p[e]; }
        if (tid < CHK) betas[tid] = beta[(size_t)chunk*CHK + tid];
    }
    __syncthreads();

    // --- row l2-norm factors ---
    if (tid < 64) {
        int r = tid & 31;
        const float* src = (tid < 32) ? (qs + r*DK) : (ks + r*DK);
        float s = 0.f;
        #pragma unroll 8
        for (int d = 0; d < DK; d++) { float x = src[d]; s += x*x; }
        rinv[tid] = rsqrtf(s + 1e-6f);
    }
    __syncthreads();

    // --- scale: qn, kn, v*beta ---
    for (int e = tid; e < 4096; e += 256) {
        int r = e >> 7;
        qs[e] *= rinv[r];
        ks[e] *= rinv[32 + r];
        vs[e] *= betas[r];
    }
    __syncthreads();

    // --- A[i][j] = -(beta_i * kn_i . kn_j) for j<i ---
    for (int o = tid; o < 1024; o += 256) {
        int i = o >> 5, j = o & 31;
        float val = 0.f;
        if (j < i) {
            const float4* a4 = (const float4*)(ks + i*DK);
            const float4* b4 = (const float4*)(ks + j*DK);
            float s = 0.f;
            #pragma unroll 8
            for (int m = 0; m < 32; m++) {
                float4 a = a4[m], b = b4[m];
                s += a.x*b.x + a.y*b.y + a.z*b.z + a.w*b.w;
            }
            val = -betas[i] * s;
        }
        A[o] = val;
    }
    __syncthreads();

    // --- forward substitution: invert (I - A), strictly-lower A (warp 0) ---
    if (tid < 32) {
        for (int i = 1; i < CHK; i++) {
            float upd = 0.f;
            if (tid < i) {
                for (int j = 0; j < i; j++) upd += A[i*CHK + j] * A[j*CHK + tid];
            }
            __syncwarp();
            if (tid < i) A[i*CHK + tid] += upd;
            __syncwarp();
        }
    }
    __syncthreads();

    // --- add I, round-trip through bf16 ---
    for (int o = tid; o < 1024; o += 256) {
        int i = o >> 5, j = o & 31;
        float val = A[o] + ((i == j) ? 1.f : 0.f);
        A[o] = __bfloat162float(__float2bfloat16(val));
    }
    __syncthreads();

    // --- u = A @ (v*beta) -> g_u (coalesced) ; w -> stage (dup, negated) ---
    {
        int i  = tid >> 3;
        int cb = (tid & 7) * 16;
        float ua[16], wa[16];
        #pragma unroll
        for (int m = 0; m < 16; m++) { ua[m] = 0.f; wa[m] = 0.f; }
        for (int t = 0; t < CHK; t++) {
            float a  = A[i*CHK + t];
            float ab = a * betas[t];
            const float* vr = vs + t*DV + cb;
            const float* kr = ks + t*DK + cb;
            #pragma unroll
            for (int m = 0; m < 16; m++) { ua[m] += a*vr[m]; wa[m] += ab*kr[m]; }
        }
        float* up = g_u + (size_t)chunk*4096 + i*DV + cb;
        #pragma unroll
        for (int m = 0; m < 16; m += 4)
            *(float4*)(up + m) = make_float4(ua[m], ua[m+1], ua[m+2], ua[m+3]);
        #pragma unroll
        for (int m = 0; m < 16; m += 2) {
            int dd = (cb + m) >> 1;
            *(float4*)(stage + dd*PW + i*4) =
                make_float4(-wa[m], -wa[m], -wa[m+1], -wa[m+1]);
        }
    }
    __syncthreads();
    // copy w4 out (coalesced)
    for (int e = tid; e < 2048; e += 256) {
        int dd = e >> 5, ii = e & 31;
        *(float4*)(g_w4 + (size_t)chunk*8192 + e*4) = *(const float4*)(stage + dd*PW + ii*4);
    }
    __syncthreads();

    // --- q4 dup via stage ---
    for (int idx = tid; idx < 2048; idx += 256) {
        int ii = idx >> 6, dd = idx & 63;
        float2 ab = *(const float2*)(qs + ii*DK + 2*dd);
        *(float4*)(stage + dd*PW + ii*4) = make_float4(ab.x, ab.x, ab.y, ab.y);
    }
    __syncthreads();
    for (int e = tid; e < 2048; e += 256) {
        int dd = e >> 5, ii = e & 31;
        *(float4*)(g_q4 + (size_t)chunk*8192 + e*4) = *(const float4*)(stage + dd*PW + ii*4);
    }
    __syncthreads();

    // --- k4 dup via stage ---
    for (int idx = tid; idx < 2048; idx += 256) {
        int ii = idx >> 6, dp = idx & 63;
        float2 ab = *(const float2*)(ks + ii*DK + 2*dp);
        *(float4*)(stage + ii*PK + dp*4) = make_float4(ab.x, ab.x, ab.y, ab.y);
    }
    __syncthreads();
    for (int e = tid; e < 2048; e += 256) {
        int ii = e >> 6, dp = e & 63;
        *(float4*)(g_k4 + (size_t)chunk*8192 + e*4) = *(const float4*)(stage + ii*PK + dp*4);
    }
    __syncthreads();

    // --- att_local = tril(qn @ kn^T) incl diag -> vs[0:1024] ---
    float* attS = vs;
    for (int o = tid; o < 1024; o += 256) {
        int i = o >> 5, j = o & 31;
        float val = 0.f;
        if (j <= i) {
            const float4* a4 = (const float4*)(qs + i*DK);
            const float4* b4 = (const float4*)(ks + j*DK);
            float s = 0.f;
            #pragma unroll 8
            for (int m = 0; m < 32; m++) {
                float4 a = a4[m], b = b4[m];
                s += a.x*b.x + a.y*b.y + a.z*b.z + a.w*b.w;
            }
            val = s;
        }
        attS[o] = val;
    }
    __syncthreads();
    for (int idx = tid; idx < 512; idx += 256) {
        int ii = idx >> 4, tt = idx & 15;
        float2 ab = *(const float2*)(attS + ii*32 + 2*tt);
        *(float4*)(stage + tt*PW + ii*4) = make_float4(ab.x, ab.x, ab.y, ab.y);
    }
    __syncthreads();
    for (int e = tid; e < 512; e += 256) {
        int tt = e >> 5, ii = e & 31;
        *(float4*)(g_a4 + (size_t)chunk*2048 + e*4) = *(const float4*)(stage + tt*PW + ii*4);
    }
}

// ============================================================================
// Kernel 2: serial scan. 128 CTAs = 16 (b,h) x 8 column blocks (16 cols each).
// S slice [128 x 16] in smem. f32x2 FMA + cp.async double-buffered staging.
// ============================================================================
#define SM_S    0        // 2048
#define SM_W4   2048     // 8192
#define SM_Q4   10240    // 8192
#define SM_K4   18432    // 2 x 8192
#define SM_A4   34816    // 2 x 2048
#define SM_UST  38912    // 2 x 512
#define SM_UN   39936    // 512
#define SM_TOT  40448

__global__ __launch_bounds__(256, 1) void scan_kernel(float* __restrict__ out, int write_state)
{
    extern __shared__ float sm[];
    float* S  = sm + SM_S;
    float* W4 = sm + SM_W4;
    float* Q4 = sm + SM_Q4;
    float* K4 = sm + SM_K4;
    float* A4 = sm + SM_A4;
    float* UST= sm + SM_UST;
    float* UN = sm + SM_UN;

    const int tid = threadIdx.x;
    const int bh = blockIdx.x >> 3;
    const int j0 = (blockIdx.x & 7) * 16;

    for (int e = tid; e < 2048; e += 256) S[e] = 0.f;

    // pass-1 / o mapping: row i1, col pair c1..c1+1
    const int i1 = tid >> 3;
    const int c1 = (tid & 7) * 2;
    // pass-2b S-update: rows 2*dp, 2*dp+1, cols c2..c2+3
    const int dp = tid >> 2;
    const int c2 = (tid & 3) * 4;

    const size_t cbase = (size_t)bh * NCHUNK;

    // ---- initial stage (chunk 0 -> buffer 0) ----
    {
        const size_t ch = cbase;
        uint32_t sw = (uint32_t)__cvta_generic_to_shared(W4);
        uint32_t sq = (uint32_t)__cvta_generic_to_shared(Q4);
        uint32_t sk = (uint32_t)__cvta_generic_to_shared(K4);
        uint32_t sa = (uint32_t)__cvta_generic_to_shared(A4);
        uint32_t su = (uint32_t)__cvta_generic_to_shared(UST);
        const float4* gw = (const float4*)(g_w4 + ch*8192);
        const float4* gq = (const float4*)(g_q4 + ch*8192);
        const float4* gk = (const float4*)(g_k4 + ch*8192);
        const float4* ga = (const float4*)(g_a4 + ch*2048);
        for (int e = tid; e < 2048; e += 256) {
            cpa16(sw + e*16, gw + e);
            cpa16(sq + e*16, gq + e);
            cpa16(sk + e*16, gk + e);
        }
        for (int e = tid; e < 512; e += 256) cpa16(sa + e*16, ga + e);
        cpa8(su + tid*8, g_u + ch*4096 + (tid>>3)*DV + j0 + (tid&7)*2);
        cpa_commit();
        cpa_wait0();
    }
    __syncthreads();

    for (int t = 0; t < NCHUNK; t++) {
        const int buf = t & 1;
        const int nbuf = buf ^ 1;
        const float* K4b  = K4  + buf*8192;
        const float* A4b  = A4  + buf*2048;
        const float* USTb = UST + buf*512;

        // ---- Pass 1 (fused): u_new = u - w@S ; o_part = q@S ----
        u64t ua, ub = 0ull, oa = 0ull, ob = 0ull;
        ua = *(const u64t*)(USTb + i1*16 + c1);
        #pragma unroll 8
        for (int dd = 0; dd < 64; dd++) {
            const ulonglong2 wv = *(const ulonglong2*)(W4 + dd*128 + i1*4);
            const ulonglong2 qv = *(const ulonglong2*)(Q4 + dd*128 + i1*4);
            const u64t s0 = *(const u64t*)(S + (2*dd  )*16 + c1);
            const u64t s1 = *(const u64t*)(S + (2*dd+1)*16 + c1);
            ffma2(ua, wv.x, s0); ffma2(ub, wv.y, s1);
            ffma2(oa, qv.x, s0); ffma2(ob, qv.y, s1);
        }
        *(u64t*)(UN + i1*16 + c1) = addf2(ua, ub);
        __syncthreads();   // UN visible; W4/Q4/UST[buf] free for prefetch

        // ---- prefetch chunk t+1 (overlaps pass 2) ----
        {
            const size_t ch = cbase + ((t+1 < NCHUNK) ? (t+1) : t);
            uint32_t sw = (uint32_t)__cvta_generic_to_shared(W4);
            uint32_t sq = (uint32_t)__cvta_generic_to_shared(Q4);
            uint32_t sk = (uint32_t)__cvta_generic_to_shared(K4 + nbuf*8192);
            uint32_t sa = (uint32_t)__cvta_generic_to_shared(A4 + nbuf*2048);
            uint32_t su = (uint32_t)__cvta_generic_to_shared(UST + nbuf*512);
            const float4* gw = (const float4*)(g_w4 + ch*8192);
            const float4* gq = (const float4*)(g_q4 + ch*8192);
            const float4* gk = (const float4*)(g_k4 + ch*8192);
            const float4* ga = (const float4*)(g_a4 + ch*2048);
            for (int e = tid; e < 2048; e += 256) {
                cpa16(sw + e*16, gw + e);
                cpa16(sq + e*16, gq + e);
                cpa16(sk + e*16, gk + e);
            }
            for (int e = tid; e < 512; e += 256) cpa16(sa + e*16, ga + e);
            cpa8(su + tid*8, g_u + ch*4096 + (tid>>3)*DV + j0 + (tid&7)*2);
            cpa_commit();
        }

        // ---- Pass 2a: o = o_part + att_local @ u_new ; write out ----
        #pragma unroll 4
        for (int tt = 0; tt < 16; tt++) {
            const ulonglong2 av = *(const ulonglong2*)(A4b + tt*128 + i1*4);
            const u64t n0 = *(const u64t*)(UN + (2*tt  )*16 + c1);
            const u64t n1 = *(const u64t*)(UN + (2*tt+1)*16 + c1);
            ffma2(oa, av.x, n0); ffma2(ob, av.y, n1);
        }
        *(u64t*)(out + ((size_t)bh*SEQ + (size_t)t*CHK + i1)*DV + j0 + c1) = addf2(oa, ob);

        // ---- Pass 2b: S += k^T @ u_new ----
        {
            u64t a00, a01, a10, a11;
            a00 = *(const u64t*)(S + (2*dp  )*16 + c2);
            a01 = *(const u64t*)(S + (2*dp  )*16 + c2 + 2);
            a10 = *(const u64t*)(S + (2*dp+1)*16 + c2);
            a11 = *(const u64t*)(S + (2*dp+1)*16 + c2 + 2);
            #pragma unroll 8
            for (int i = 0; i < CHK; i++) {
                const ulonglong2 kv = *(const ulonglong2*)(K4b + i*256 + dp*4);
                const ulonglong2 na = *(const ulonglong2*)(UN + i*16 + c2);
                ffma2(a00, kv.x, na.x); ffma2(a01, kv.x, na.y);
                ffma2(a10, kv.y, na.x); ffma2(a11, kv.y, na.y);
            }
            *(u64t*)(S + (2*dp  )*16 + c2    ) = a00;
            *(u64t*)(S + (2*dp  )*16 + c2 + 2) = a01;
            *(u64t*)(S + (2*dp+1)*16 + c2    ) = a10;
            *(u64t*)(S + (2*dp+1)*16 + c2 + 2) = a11;
        }

        cpa_wait0();
        __syncthreads();   // S updated + next chunk staged
    }

    // ---- optional final-state output (reference returns (o, S)) ----
    if (write_state) {
        const int d = tid >> 1;
        const int c = (tid & 1) * 8;
        *(float4*)(out + (size_t)O_ELEMS + (size_t)bh*(DK*DV) + d*DV + j0 + c) =
            *(const float4*)(S + d*16 + c);
        *(float4*)(out + (size_t)O_ELEMS + (size_t)bh*(DK*DV) + d*DV + j0 + c + 4) =
            *(const float4*)(S + d*16 + c + 4);
    }
}

// ============================================================================
extern "C" void kernel_launch(void* const* d_in, const int* in_sizes, int n_in,
                              void* d_out, int out_size) {
    const float* q    = (const float*)d_in[0];
    const float* k    = (const float*)d_in[1];
    const float* v    = (const float*)d_in[2];
    const float* beta = (const float*)d_in[3];
    float* out = (float*)d_out;

    const int smem1 = P_TOT * 4;     // 87424 B
    const int smem2 = SM_TOT * 4;    // 161792 B
    cudaFuncSetAttribute(prep_kernel, cudaFuncAttributeMaxDynamicSharedMemorySize, smem1);
    cudaFuncSetAttribute(scan_kernel, cudaFuncAttributeMaxDynamicSharedMemorySize, smem2);

    const int write_state = (out_size >= O_ELEMS + S_ELEMS) ? 1 : 0;

    prep_kernel<<<TOTAL_CHUNKS, 256, smem1>>>(q, k, v, beta);
    scan_kernel<<<BHN*8, 256, smem2>>>(out, write_state);
}

// round 5
// speedup vs baseline: 1.9033x; 1.2213x over previous
#include <cuda_runtime.h>
#include <cuda_bf16.h>
#include <cstdint>

#define NB 2
#define NH 8
#define SEQ 4096
#define DK 128
#define DV 128
#define CHK 32
#define NCHUNK 128                 // chunks per (b,h)
#define BHN (NB*NH)                // 16
#define TOTAL_CHUNKS (BHN*NCHUNK)  // 2048
#define O_ELEMS (NB*NH*SEQ*DV)     // 8388608
#define S_ELEMS (NB*NH*DK*DV)      // 262144

// ---- scratch (static device arrays; no runtime allocation) ----
__device__ float g_w4[(size_t)TOTAL_CHUNKS*8192];
__device__ float g_q4[(size_t)TOTAL_CHUNKS*8192];
__device__ float g_k4[(size_t)TOTAL_CHUNKS*8192];
__device__ float g_a4[(size_t)TOTAL_CHUNKS*2048];
__device__ float g_u [(size_t)TOTAL_CHUNKS*4096];

typedef unsigned long long u64t;

__device__ __forceinline__ void ffma2(u64t& d, u64t a, u64t b) {
    asm("fma.rn.f32x2 %0, %1, %2, %0;" : "+l"(d) : "l"(a), "l"(b));
}
__device__ __forceinline__ u64t addf2(u64t a, u64t b) {
    u64t d; asm("add.rn.f32x2 %0, %1, %2;" : "=l"(d) : "l"(a), "l"(b)); return d;
}
__device__ __forceinline__ void cpa16(uint32_t s, const void* g) {
    asm volatile("cp.async.cg.shared.global [%0], [%1], 16;" :: "r"(s), "l"(g));
}
__device__ __forceinline__ void cpa8(uint32_t s, const void* g) {
    asm volatile("cp.async.ca.shared.global [%0], [%1], 8;" :: "r"(s), "l"(g));
}
__device__ __forceinline__ void cpa_commit() { asm volatile("cp.async.commit_group;"); }
__device__ __forceinline__ void cpa_wait0()  { asm volatile("cp.async.wait_group 0;" ::: "memory"); }

// ============================================================================
// Kernel 1: per-chunk preprocessing (2048 CTAs x 256 threads).
// Bank-conflict-free: transposed operands for dot products, shuffle norms.
// smem layout (floats):
//   qs [32][132]  @ 0       (4224)
//   ks [32][132]  @ 4224    (4224)
//   vs [32][132]  @ 8448    (4224)
//   kT [128][36]  @ 12672   (4608)   } region reused as stage (8448) later
//   qT [128][36]  @ 17280   (4608)   }
//   A  [32][32]   @ 21888   (1024)
//   betas         @ 22912   (32)
//   rinv          @ 22944   (64)
//   attS [32][32] @ 23008   (1024)
#define RS 132
#define TS 36
#define OF_QS 0
#define OF_KS 4224
#define OF_VS 8448
#define OF_KT 12672
#define OF_QT 17280
#define OF_A  21888
#define OF_B  22912
#define OF_R  22944
#define OF_AT 23008
#define PW 132   // stage row stride (floats)
#define PK 260
#define P_TOT 24032

__global__ __launch_bounds__(256) void prep_kernel(
    const float* __restrict__ q, const float* __restrict__ k,
    const float* __restrict__ v, const float* __restrict__ beta)
{
    extern __shared__ float sm[];
    float* qs    = sm + OF_QS;
    float* ks    = sm + OF_KS;
    float* vs    = sm + OF_VS;
    float* kT    = sm + OF_KT;
    float* qT    = sm + OF_QT;
    float* A     = sm + OF_A;
    float* betas = sm + OF_B;
    float* rinv  = sm + OF_R;
    float* attS  = sm + OF_AT;
    float* stage = sm + OF_KT;   // reuse kT/qT region after att is computed

    const int tid  = threadIdx.x;
    const int lane = tid & 31;
    const int wid  = tid >> 5;
    const int chunk = blockIdx.x;
    const size_t base = (size_t)chunk * (CHK*DK);

    // --- load q,k,v tile into padded rows (coalesced) + beta ---
    for (int e = tid; e < 1024; e += 256) {
        int r = e >> 5, c4 = (e & 31) * 4;
        float4 a = *(const float4*)(q + base + r*DK + c4);
        float4 b = *(const float4*)(k + base + r*DK + c4);
        float4 cvv = *(const float4*)(v + base + r*DK + c4);
        *(float4*)(qs + r*RS + c4) = a;
        *(float4*)(ks + r*RS + c4) = b;
        *(float4*)(vs + r*RS + c4) = cvv;
    }
    if (tid < CHK) betas[tid] = beta[(size_t)chunk*CHK + tid];
    __syncthreads();

    // --- row l2-norm factors via warp shuffle (8 warps x 8 rows) ---
    {
        // warps 0..3: q rows, warps 4..7: k rows. Each warp: 8 rows.
        const float* srcb = (wid < 4) ? qs : ks;
        int rbase = (wid & 3) * 8;
        #pragma unroll
        for (int rr = 0; rr < 8; rr++) {
            int r = rbase + rr;
            float4 x = *(const float4*)(srcb + r*RS + lane*4);
            float s = x.x*x.x + x.y*x.y + x.z*x.z + x.w*x.w;
            #pragma unroll
            for (int off = 16; off > 0; off >>= 1)
                s += __shfl_xor_sync(0xffffffffu, s, off);
            if (lane == 0) rinv[((wid < 4) ? 0 : 32) + r] = rsqrtf(s + 1e-6f);
        }
    }
    __syncthreads();

    // --- scale rows: qn, kn, v*beta ---
    for (int e = tid; e < 4096; e += 256) {
        int r = e >> 7, c = e & 127;
        qs[r*RS + c] *= rinv[r];
        ks[r*RS + c] *= rinv[32 + r];
        vs[r*RS + c] *= betas[r];
    }
    __syncthreads();

    // --- build transposes kT[d][i], qT[d][i] ---
    for (int e = tid; e < 4096; e += 256) {
        int i = e >> 7, d = e & 127;
        kT[d*TS + i] = ks[i*RS + d];
        qT[d*TS + i] = qs[i*RS + d];
    }
    __syncthreads();

    // --- A[i][j] = -(beta_i * kn_i . kn_j) (j<i), att[i][j] = qn_i . kn_j (j<=i)
    //     2x2 register tiles, conflict-free transposed loads ---
    {
        const int ti = (tid >> 4) * 2;   // rows 2ti..2ti+1
        const int tj = (tid & 15) * 2;   // cols 2tj..2tj+1
        float k00=0,k01=0,k10=0,k11=0;
        float a00=0,a01=0,a10=0,a11=0;
        #pragma unroll 8
        for (int d = 0; d < DK; d++) {
            float2 kb = *(const float2*)(kT + d*TS + tj);
            float2 ka = *(const float2*)(kT + d*TS + ti);
            float2 qa = *(const float2*)(qT + d*TS + ti);
            k00 += ka.x*kb.x; k01 += ka.x*kb.y;
            k10 += ka.y*kb.x; k11 += ka.y*kb.y;
            a00 += qa.x*kb.x; a01 += qa.x*kb.y;
            a10 += qa.y*kb.x; a11 += qa.y*kb.y;
        }
        float bi0 = betas[ti], bi1 = betas[ti+1];
        A[(ti  )*32 + tj  ] = (tj   < ti  ) ? -bi0*k00 : 0.f;
        A[(ti  )*32 + tj+1] = (tj+1 < ti  ) ? -bi0*k01 : 0.f;
        A[(ti+1)*32 + tj  ] = (tj   < ti+1) ? -bi1*k10 : 0.f;
        A[(ti+1)*32 + tj+1] = (tj+1 < ti+1) ? -bi1*k11 : 0.f;
        attS[(ti  )*32 + tj  ] = (tj   <= ti  ) ? a00 : 0.f;
        attS[(ti  )*32 + tj+1] = (tj+1 <= ti  ) ? a01 : 0.f;
        attS[(ti+1)*32 + tj  ] = (tj   <= ti+1) ? a10 : 0.f;
        attS[(ti+1)*32 + tj+1] = (tj+1 <= ti+1) ? a11 : 0.f;
    }
    __syncthreads();

    // --- forward substitution: invert (I - A), strictly-lower A (warp 0) ---
    if (tid < 32) {
        for (int i = 1; i < CHK; i++) {
            float upd = 0.f;
            if (tid < i) {
                for (int j = 0; j < i; j++) upd += A[i*CHK + j] * A[j*CHK + tid];
            }
            __syncwarp();
            if (tid < i) A[i*CHK + tid] += upd;
            __syncwarp();
        }
    }
    __syncthreads();

    // --- add I, round-trip through bf16 ---
    for (int o = tid; o < 1024; o += 256) {
        int i = o >> 5, j = o & 31;
        float val = A[o] + ((i == j) ? 1.f : 0.f);
        A[o] = __bfloat162float(__float2bfloat16(val));
    }
    __syncthreads();   // also: kT/qT dead from here -> stage region free

    // --- u = A @ (v*beta) -> g_u (coalesced) ; w -> stage (dup, negated) ---
    {
        int i  = tid >> 3;
        int cb = (tid & 7) * 16;
        float ua[16], wa[16];
        #pragma unroll
        for (int m = 0; m < 16; m++) { ua[m] = 0.f; wa[m] = 0.f; }
        for (int t = 0; t < CHK; t++) {
            float a  = A[i*CHK + t];
            float ab = a * betas[t];
            const float* vr = vs + t*RS + cb;
            const float* kr = ks + t*RS + cb;
            #pragma unroll
            for (int m = 0; m < 16; m++) { ua[m] += a*vr[m]; wa[m] += ab*kr[m]; }
        }
        float* up = g_u + (size_t)chunk*4096 + i*DV + cb;
        #pragma unroll
        for (int m = 0; m < 16; m += 4)
            *(float4*)(up + m) = make_float4(ua[m], ua[m+1], ua[m+2], ua[m+3]);
        #pragma unroll
        for (int m = 0; m < 16; m += 2) {
            int dd = (cb + m) >> 1;
            *(float4*)(stage + dd*PW + i*4) =
                make_float4(-wa[m], -wa[m], -wa[m+1], -wa[m+1]);
        }
    }
    __syncthreads();
    // copy w4 out (coalesced)
    for (int e = tid; e < 2048; e += 256) {
        int dd = e >> 5, ii = e & 31;
        *(float4*)(g_w4 + (size_t)chunk*8192 + e*4) = *(const float4*)(stage + dd*PW + ii*4);
    }
    __syncthreads();

    // --- q4 dup via stage ---
    for (int idx = tid; idx < 2048; idx += 256) {
        int ii = idx >> 6, dd = idx & 63;
        float2 ab = *(const float2*)(qs + ii*RS + 2*dd);
        *(float4*)(stage + dd*PW + ii*4) = make_float4(ab.x, ab.x, ab.y, ab.y);
    }
    __syncthreads();
    for (int e = tid; e < 2048; e += 256) {
        int dd = e >> 5, ii = e & 31;
        *(float4*)(g_q4 + (size_t)chunk*8192 + e*4) = *(const float4*)(stage + dd*PW + ii*4);
    }
    __syncthreads();

    // --- k4 dup via stage ---
    for (int idx = tid; idx < 2048; idx += 256) {
        int ii = idx >> 6, dp = idx & 63;
        float2 ab = *(const float2*)(ks + ii*RS + 2*dp);
        *(float4*)(stage + ii*PK + dp*4) = make_float4(ab.x, ab.x, ab.y, ab.y);
    }
    __syncthreads();
    for (int e = tid; e < 2048; e += 256) {
        int ii = e >> 6, dp = e & 63;
        *(float4*)(g_k4 + (size_t)chunk*8192 + e*4) = *(const float4*)(stage + ii*PK + dp*4);
    }
    __syncthreads();

    // --- att dup via stage ---
    for (int idx = tid; idx < 512; idx += 256) {
        int ii = idx >> 4, tt = idx & 15;
        float2 ab = *(const float2*)(attS + ii*32 + 2*tt);
        *(float4*)(stage + tt*PW + ii*4) = make_float4(ab.x, ab.x, ab.y, ab.y);
    }
    __syncthreads();
    for (int e = tid; e < 512; e += 256) {
        int tt = e >> 5, ii = e & 31;
        *(float4*)(g_a4 + (size_t)chunk*2048 + e*4) = *(const float4*)(stage + tt*PW + ii*4);
    }
}

// ============================================================================
// Kernel 2: serial scan. 128 CTAs = 16 (b,h) x 8 column blocks (16 cols each).
// S slice [128 x 16] in smem. f32x2 FMA + cp.async double-buffered staging.
// ============================================================================
#define SM_S    0        // 2048
#define SM_W4   2048     // 8192
#define SM_Q4   10240    // 8192
#define SM_K4   18432    // 2 x 8192
#define SM_A4   34816    // 2 x 2048
#define SM_UST  38912    // 2 x 512
#define SM_UN   39936    // 512
#define SM_TOT  40448

__global__ __launch_bounds__(256, 1) void scan_kernel(float* __restrict__ out, int write_state)
{
    extern __shared__ float sm[];
    float* S  = sm + SM_S;
    float* W4 = sm + SM_W4;
    float* Q4 = sm + SM_Q4;
    float* K4 = sm + SM_K4;
    float* A4 = sm + SM_A4;
    float* UST= sm + SM_UST;
    float* UN = sm + SM_UN;

    const int tid = threadIdx.x;
    const int bh = blockIdx.x >> 3;
    const int j0 = (blockIdx.x & 7) * 16;

    for (int e = tid; e < 2048; e += 256) S[e] = 0.f;

    // pass-1 / o mapping: row i1, col pair c1..c1+1
    const int i1 = tid >> 3;
    const int c1 = (tid & 7) * 2;
    // pass-2b S-update: rows 2*dp, 2*dp+1, cols c2..c2+3
    const int dp = tid >> 2;
    const int c2 = (tid & 3) * 4;

    const size_t cbase = (size_t)bh * NCHUNK;

    // ---- initial stage (chunk 0 -> buffer 0) ----
    {
        const size_t ch = cbase;
        uint32_t sw = (uint32_t)__cvta_generic_to_shared(W4);
        uint32_t sq = (uint32_t)__cvta_generic_to_shared(Q4);
        uint32_t sk = (uint32_t)__cvta_generic_to_shared(K4);
        uint32_t sa = (uint32_t)__cvta_generic_to_shared(A4);
        uint32_t su = (uint32_t)__cvta_generic_to_shared(UST);
        const float4* gw = (const float4*)(g_w4 + ch*8192);
        const float4* gq = (const float4*)(g_q4 + ch*8192);
        const float4* gk = (const float4*)(g_k4 + ch*8192);
        const float4* ga = (const float4*)(g_a4 + ch*2048);
        for (int e = tid; e < 2048; e += 256) {
            cpa16(sw + e*16, gw + e);
            cpa16(sq + e*16, gq + e);
            cpa16(sk + e*16, gk + e);
        }
        for (int e = tid; e < 512; e += 256) cpa16(sa + e*16, ga + e);
        cpa8(su + tid*8, g_u + ch*4096 + (tid>>3)*DV + j0 + (tid&7)*2);
        cpa_commit();
        cpa_wait0();
    }
    __syncthreads();

    for (int t = 0; t < NCHUNK; t++) {
        const int buf = t & 1;
        const int nbuf = buf ^ 1;
        const float* K4b  = K4  + buf*8192;
        const float* A4b  = A4  + buf*2048;
        const float* USTb = UST + buf*512;

        // ---- Pass 1 (fused): u_new = u - w@S ; o_part = q@S ----
        u64t ua, ub = 0ull, oa = 0ull, ob = 0ull;
        ua = *(const u64t*)(USTb + i1*16 + c1);
        #pragma unroll 8
        for (int dd = 0; dd < 64; dd++) {
            const ulonglong2 wv = *(const ulonglong2*)(W4 + dd*128 + i1*4);
            const ulonglong2 qv = *(const ulonglong2*)(Q4 + dd*128 + i1*4);
            const u64t s0 = *(const u64t*)(S + (2*dd  )*16 + c1);
            const u64t s1 = *(const u64t*)(S + (2*dd+1)*16 + c1);
            ffma2(ua, wv.x, s0); ffma2(ub, wv.y, s1);
            ffma2(oa, qv.x, s0); ffma2(ob, qv.y, s1);
        }
        *(u64t*)(UN + i1*16 + c1) = addf2(ua, ub);
        __syncthreads();   // UN visible; W4/Q4/UST[buf] free for prefetch

        // ---- prefetch chunk t+1 (overlaps pass 2) ----
        {
            const size_t ch = cbase + ((t+1 < NCHUNK) ? (t+1) : t);
            uint32_t sw = (uint32_t)__cvta_generic_to_shared(W4);
            uint32_t sq = (uint32_t)__cvta_generic_to_shared(Q4);
            uint32_t sk = (uint32_t)__cvta_generic_to_shared(K4 + nbuf*8192);
            uint32_t sa = (uint32_t)__cvta_generic_to_shared(A4 + nbuf*2048);
            uint32_t su = (uint32_t)__cvta_generic_to_shared(UST + nbuf*512);
            const float4* gw = (const float4*)(g_w4 + ch*8192);
            const float4* gq = (const float4*)(g_q4 + ch*8192);
            const float4* gk = (const float4*)(g_k4 + ch*8192);
            const float4* ga = (const float4*)(g_a4 + ch*2048);
            for (int e = tid; e < 2048; e += 256) {
                cpa16(sw + e*16, gw + e);
                cpa16(sq + e*16, gq + e);
                cpa16(sk + e*16, gk + e);
            }
            for (int e = tid; e < 512; e += 256) cpa16(sa + e*16, ga + e);
            cpa8(su + tid*8, g_u + ch*4096 + (tid>>3)*DV + j0 + (tid&7)*2);
            cpa_commit();
        }

        // ---- Pass 2a: o = o_part + att_local @ u_new ; write out ----
        #pragma unroll 4
        for (int tt = 0; tt < 16; tt++) {
            const ulonglong2 av = *(const ulonglong2*)(A4b + tt*128 + i1*4);
            const u64t n0 = *(const u64t*)(UN + (2*tt  )*16 + c1);
            const u64t n1 = *(const u64t*)(UN + (2*tt+1)*16 + c1);
            ffma2(oa, av.x, n0); ffma2(ob, av.y, n1);
        }
        *(u64t*)(out + ((size_t)bh*SEQ + (size_t)t*CHK + i1)*DV + j0 + c1) = addf2(oa, ob);

        // ---- Pass 2b: S += k^T @ u_new ----
        {
            u64t a00, a01, a10, a11;
            a00 = *(const u64t*)(S + (2*dp  )*16 + c2);
            a01 = *(const u64t*)(S + (2*dp  )*16 + c2 + 2);
            a10 = *(const u64t*)(S + (2*dp+1)*16 + c2);
            a11 = *(const u64t*)(S + (2*dp+1)*16 + c2 + 2);
            #pragma unroll 8
            for (int i = 0; i < CHK; i++) {
                const ulonglong2 kv = *(const ulonglong2*)(K4b + i*256 + dp*4);
                const ulonglong2 na = *(const ulonglong2*)(UN + i*16 + c2);
                ffma2(a00, kv.x, na.x); ffma2(a01, kv.x, na.y);
                ffma2(a10, kv.y, na.x); ffma2(a11, kv.y, na.y);
            }
            *(u64t*)(S + (2*dp  )*16 + c2    ) = a00;
            *(u64t*)(S + (2*dp  )*16 + c2 + 2) = a01;
            *(u64t*)(S + (2*dp+1)*16 + c2    ) = a10;
            *(u64t*)(S + (2*dp+1)*16 + c2 + 2) = a11;
        }

        cpa_wait0();
        __syncthreads();   // S updated + next chunk staged
    }

    // ---- optional final-state output (reference returns (o, S)) ----
    if (write_state) {
        const int d = tid >> 1;
        const int c = (tid & 1) * 8;
        *(float4*)(out + (size_t)O_ELEMS + (size_t)bh*(DK*DV) + d*DV + j0 + c) =
            *(const float4*)(S + d*16 + c);
        *(float4*)(out + (size_t)O_ELEMS + (size_t)bh*(DK*DV) + d*DV + j0 + c + 4) =
            *(const float4*)(S + d*16 + c + 4);
    }
}

// ============================================================================
extern "C" void kernel_launch(void* const* d_in, const int* in_sizes, int n_in,
                              void* d_out, int out_size) {
    const float* q    = (const float*)d_in[0];
    const float* k    = (const float*)d_in[1];
    const float* v    = (const float*)d_in[2];
    const float* beta = (const float*)d_in[3];
    float* out = (float*)d_out;

    const int smem1 = P_TOT * 4;     // 96128 B
    const int smem2 = SM_TOT * 4;    // 161792 B
    cudaFuncSetAttribute(prep_kernel, cudaFuncAttributeMaxDynamicSharedMemorySize, smem1);
    cudaFuncSetAttribute(scan_kernel, cudaFuncAttributeMaxDynamicSharedMemorySize, smem2);

    const int write_state = (out_size >= O_ELEMS + S_ELEMS) ? 1 : 0;

    prep_kernel<<<TOTAL_CHUNKS, 256, smem1>>>(q, k, v, beta);
    scan_kernel<<<BHN*8, 256, smem2>>>(out, write_state);
}

// round 6
// speedup vs baseline: 2.0538x; 1.0791x over previous
#include <cuda_runtime.h>
#include <cuda_bf16.h>
#include <cstdint>

#define NB 2
#define NH 8
#define SEQ 4096
#define DK 128
#define DV 128
#define CHK 32
#define NCHUNK 128
#define BHN (NB*NH)
#define TOTAL_CHUNKS (BHN*NCHUNK)  // 2048
#define O_ELEMS (NB*NH*SEQ*DV)
#define S_ELEMS (NB*NH*DK*DV)

// ---- scratch ----
// g_w4[chunk][dd][i][4] = dup quads of -w ; g_q4 same for q (dd=0..63)
// g_k [chunk][i][d]     plain k rows
// g_a [chunk][i][t]     plain att rows (32x32)
// g_u [chunk][i][j]     u = T @ (v*beta)
__device__ float g_w4[(size_t)TOTAL_CHUNKS*8192];
__device__ float g_q4[(size_t)TOTAL_CHUNKS*8192];
__device__ float g_k [(size_t)TOTAL_CHUNKS*4096];
__device__ float g_a [(size_t)TOTAL_CHUNKS*1024];
__device__ float g_u [(size_t)TOTAL_CHUNKS*4096];

typedef unsigned long long u64t;

__device__ __forceinline__ void ffma2(u64t& d, u64t a, u64t b) {
    asm("fma.rn.f32x2 %0, %1, %2, %0;" : "+l"(d) : "l"(a), "l"(b));
}
__device__ __forceinline__ u64t addf2(u64t a, u64t b) {
    u64t d; asm("add.rn.f32x2 %0, %1, %2;" : "=l"(d) : "l"(a), "l"(b)); return d;
}
__device__ __forceinline__ u64t dupf(float x) {
    u64t d; asm("mov.b64 %0, {%1, %1};" : "=l"(d) : "f"(x)); return d;
}
__device__ __forceinline__ void cpa16(uint32_t s, const void* g) {
    asm volatile("cp.async.cg.shared.global [%0], [%1], 16;" :: "r"(s), "l"(g));
}
__device__ __forceinline__ void cpa8(uint32_t s, const void* g) {
    asm volatile("cp.async.ca.shared.global [%0], [%1], 8;" :: "r"(s), "l"(g));
}
__device__ __forceinline__ void cpa_commit() { asm volatile("cp.async.commit_group;"); }
__device__ __forceinline__ void cpa_wait0()  { asm volatile("cp.async.wait_group 0;" ::: "memory"); }

__global__ void noop_kernel() {}

// ============================================================================
// Kernel 1: per-chunk preprocessing (2048 CTAs x 256 threads)
// ============================================================================
#define RS 132
#define TS 36
#define OF_QS 0
#define OF_KS 4224
#define OF_VS 8448
#define OF_KT 12672
#define OF_QT 17280
#define OF_A  21888
#define OF_B  22912
#define OF_R  22944
#define OF_AT 23008
#define PW 132
#define P_TOT 24032

__global__ __launch_bounds__(256) void prep_kernel(
    const float* __restrict__ q, const float* __restrict__ k,
    const float* __restrict__ v, const float* __restrict__ beta)
{
    extern __shared__ float sm[];
    float* qs    = sm + OF_QS;
    float* ks    = sm + OF_KS;
    float* vs    = sm + OF_VS;
    float* kT    = sm + OF_KT;
    float* qT    = sm + OF_QT;
    float* A     = sm + OF_A;
    float* betas = sm + OF_B;
    float* rinv  = sm + OF_R;
    float* attS  = sm + OF_AT;
    float* stage = sm + OF_KT;   // reuse kT/qT region after att computed

    const int tid  = threadIdx.x;
    const int lane = tid & 31;
    const int wid  = tid >> 5;
    const int chunk = blockIdx.x;
    const size_t base = (size_t)chunk * (CHK*DK);

    for (int e = tid; e < 1024; e += 256) {
        int r = e >> 5, c4 = (e & 31) * 4;
        *(float4*)(qs + r*RS + c4) = *(const float4*)(q + base + r*DK + c4);
        *(float4*)(ks + r*RS + c4) = *(const float4*)(k + base + r*DK + c4);
        *(float4*)(vs + r*RS + c4) = *(const float4*)(v + base + r*DK + c4);
    }
    if (tid < CHK) betas[tid] = beta[(size_t)chunk*CHK + tid];
    __syncthreads();

    // row l2-norm factors via warp shuffle
    {
        const float* srcb = (wid < 4) ? qs : ks;
        int rbase = (wid & 3) * 8;
        #pragma unroll
        for (int rr = 0; rr < 8; rr++) {
            int r = rbase + rr;
            float4 x = *(const float4*)(srcb + r*RS + lane*4);
            float s = x.x*x.x + x.y*x.y + x.z*x.z + x.w*x.w;
            #pragma unroll
            for (int off = 16; off > 0; off >>= 1)
                s += __shfl_xor_sync(0xffffffffu, s, off);
            if (lane == 0) rinv[((wid < 4) ? 0 : 32) + r] = rsqrtf(s + 1e-6f);
        }
    }
    __syncthreads();

    for (int e = tid; e < 4096; e += 256) {
        int r = e >> 7, c = e & 127;
        qs[r*RS + c] *= rinv[r];
        ks[r*RS + c] *= rinv[32 + r];
        vs[r*RS + c] *= betas[r];
    }
    __syncthreads();

    // transposes for conflict-free dots
    for (int e = tid; e < 4096; e += 256) {
        int i = e >> 7, d = e & 127;
        kT[d*TS + i] = ks[i*RS + d];
        qT[d*TS + i] = qs[i*RS + d];
    }
    __syncthreads();

    // A and att 2x2 tiles
    {
        const int ti = (tid >> 4) * 2;
        const int tj = (tid & 15) * 2;
        float k00=0,k01=0,k10=0,k11=0;
        float a00=0,a01=0,a10=0,a11=0;
        #pragma unroll 8
        for (int d = 0; d < DK; d++) {
            float2 kb = *(const float2*)(kT + d*TS + tj);
            float2 ka = *(const float2*)(kT + d*TS + ti);
            float2 qa = *(const float2*)(qT + d*TS + ti);
            k00 += ka.x*kb.x; k01 += ka.x*kb.y;
            k10 += ka.y*kb.x; k11 += ka.y*kb.y;
            a00 += qa.x*kb.x; a01 += qa.x*kb.y;
            a10 += qa.y*kb.x; a11 += qa.y*kb.y;
        }
        float bi0 = betas[ti], bi1 = betas[ti+1];
        A[(ti  )*32 + tj  ] = (tj   < ti  ) ? -bi0*k00 : 0.f;
        A[(ti  )*32 + tj+1] = (tj+1 < ti  ) ? -bi0*k01 : 0.f;
        A[(ti+1)*32 + tj  ] = (tj   < ti+1) ? -bi1*k10 : 0.f;
        A[(ti+1)*32 + tj+1] = (tj+1 < ti+1) ? -bi1*k11 : 0.f;
        attS[(ti  )*32 + tj  ] = (tj   <= ti  ) ? a00 : 0.f;
        attS[(ti  )*32 + tj+1] = (tj+1 <= ti  ) ? a01 : 0.f;
        attS[(ti+1)*32 + tj  ] = (tj   <= ti+1) ? a10 : 0.f;
        attS[(ti+1)*32 + tj+1] = (tj+1 <= ti+1) ? a11 : 0.f;
    }
    __syncthreads();

    // forward substitution (warp 0)
    if (tid < 32) {
        for (int i = 1; i < CHK; i++) {
            float upd = 0.f;
            if (tid < i) {
                for (int j = 0; j < i; j++) upd += A[i*CHK + j] * A[j*CHK + tid];
            }
            __syncwarp();
            if (tid < i) A[i*CHK + tid] += upd;
            __syncwarp();
        }
    }
    __syncthreads();

    // add I, bf16 round-trip
    for (int o = tid; o < 1024; o += 256) {
        int i = o >> 5, j = o & 31;
        float val = A[o] + ((i == j) ? 1.f : 0.f);
        A[o] = __bfloat162float(__float2bfloat16(val));
    }
    __syncthreads();   // kT/qT dead -> stage region free

    // u -> g_u ; w -> stage (dup quads, negated)
    {
        int i  = tid >> 3;
        int cb = (tid & 7) * 16;
        float ua[16], wa[16];
        #pragma unroll
        for (int m = 0; m < 16; m++) { ua[m] = 0.f; wa[m] = 0.f; }
        for (int t = 0; t < CHK; t++) {
            float a  = A[i*CHK + t];
            float ab = a * betas[t];
            const float* vr = vs + t*RS + cb;
            const float* kr = ks + t*RS + cb;
            #pragma unroll
            for (int m = 0; m < 16; m++) { ua[m] += a*vr[m]; wa[m] += ab*kr[m]; }
        }
        float* up = g_u + (size_t)chunk*4096 + i*DV + cb;
        #pragma unroll
        for (int m = 0; m < 16; m += 4)
            *(float4*)(up + m) = make_float4(ua[m], ua[m+1], ua[m+2], ua[m+3]);
        #pragma unroll
        for (int m = 0; m < 16; m += 2) {
            int dd = (cb + m) >> 1;
            *(float4*)(stage + dd*PW + i*4) =
                make_float4(-wa[m], -wa[m], -wa[m+1], -wa[m+1]);
        }
    }
    __syncthreads();
    for (int e = tid; e < 2048; e += 256) {
        int dd = e >> 5, ii = e & 31;
        *(float4*)(g_w4 + (size_t)chunk*8192 + e*4) = *(const float4*)(stage + dd*PW + ii*4);
    }
    __syncthreads();

    // q dup quads via stage
    for (int idx = tid; idx < 2048; idx += 256) {
        int ii = idx >> 6, dd = idx & 63;
        float2 ab = *(const float2*)(qs + ii*RS + 2*dd);
        *(float4*)(stage + dd*PW + ii*4) = make_float4(ab.x, ab.x, ab.y, ab.y);
    }
    __syncthreads();
    for (int e = tid; e < 2048; e += 256) {
        int dd = e >> 5, ii = e & 31;
        *(float4*)(g_q4 + (size_t)chunk*8192 + e*4) = *(const float4*)(stage + dd*PW + ii*4);
    }

    // plain k rows
    for (int e = tid; e < 1024; e += 256) {
        int r = e >> 5, c4 = (e & 31) * 4;
        *(float4*)(g_k + (size_t)chunk*4096 + r*128 + c4) = *(const float4*)(ks + r*RS + c4);
    }
    // plain att rows (contiguous 32x32)
    for (int e = tid; e < 256; e += 256) {
        *(float4*)(g_a + (size_t)chunk*1024 + e*4) = *(const float4*)(attS + e*4);
    }
}

// ============================================================================
// Kernel 2: serial scan. 128 CTAs = 16 bh x 8 col blocks (16 cols).
// Split-K pass1, split-T pass2a, plain k/att with register dup packing.
// ============================================================================
#define SM_S    0        // 2048
#define SM_W4   2048     // 8192
#define SM_Q4   10240    // 8192
#define SM_K    18432    // 2 x 4096
#define SM_AT   26624    // 2 x 1024
#define SM_UST  28672    // 2 x 512
#define SM_CMB  29696    // 1024
#define SM_UN   30720    // 512
#define SM_TOT  31232

__global__ __launch_bounds__(256, 1) void scan_kernel(float* __restrict__ out, int write_state)
{
    extern __shared__ float sm[];
    float* S  = sm + SM_S;
    float* W4 = sm + SM_W4;
    float* Q4 = sm + SM_Q4;
    float* K  = sm + SM_K;
    float* AT = sm + SM_AT;
    float* UST= sm + SM_UST;
    float* CMB= sm + SM_CMB;
    float* UN = sm + SM_UN;

    const int tid = threadIdx.x;
    const int bh = blockIdx.x >> 3;
    const int j0 = (blockIdx.x & 7) * 16;

    // split-K pass1 mapping
    const int kh = tid >> 7;          // 0: d 0..63, 1: d 64..127
    const int r  = (tid >> 2) & 31;   // row 0..31
    const int cq = (tid & 3) * 4;     // 4 cols
    const int lid128 = tid & 127;
    // pass2b mapping
    const int dp = tid >> 2;          // S rows 2dp, 2dp+1
    const int c2 = (tid & 3) * 4;

    for (int e = tid; e < 2048; e += 256) S[e] = 0.f;

    const size_t cbase = (size_t)bh * NCHUNK;

    // initial stage (chunk 0 -> buffer 0)
    {
        const size_t ch = cbase;
        uint32_t sw = (uint32_t)__cvta_generic_to_shared(W4);
        uint32_t sq = (uint32_t)__cvta_generic_to_shared(Q4);
        uint32_t sk = (uint32_t)__cvta_generic_to_shared(K);
        uint32_t sa = (uint32_t)__cvta_generic_to_shared(AT);
        uint32_t su = (uint32_t)__cvta_generic_to_shared(UST);
        const float4* gw = (const float4*)(g_w4 + ch*8192);
        const float4* gq = (const float4*)(g_q4 + ch*8192);
        const float4* gk = (const float4*)(g_k  + ch*4096);
        const float4* ga = (const float4*)(g_a  + ch*1024);
        for (int e = tid; e < 2048; e += 256) { cpa16(sw + e*16, gw + e); cpa16(sq + e*16, gq + e); }
        for (int e = tid; e < 1024; e += 256) cpa16(sk + e*16, gk + e);
        for (int e = tid; e < 256;  e += 256) cpa16(sa + e*16, ga + e);
        cpa8(su + tid*8, g_u + ch*4096 + (tid>>3)*DV + j0 + (tid&7)*2);
        cpa_commit();
        cpa_wait0();
    }
    __syncthreads();

    for (int t = 0; t < NCHUNK; t++) {
        const int buf = t & 1;
        const int nbuf = buf ^ 1;
        const float* Kb  = K  + buf*4096;
        const float* ATb = AT + buf*1024;
        const float* USTb= UST+ buf*512;

        // ---- Pass 1 (split-K): u_new = u - w@S ; o_part = q@S ----
        u64t u0, u1, o0 = 0ull, o1 = 0ull;
        if (kh == 0) {
            ulonglong2 uu = *(const ulonglong2*)(USTb + r*16 + cq);
            u0 = uu.x; u1 = uu.y;
        } else { u0 = 0ull; u1 = 0ull; }
        {
            const int d0 = kh * 32;
            #pragma unroll 8
            for (int m = 0; m < 32; m++) {
                int dd = d0 + m;
                const ulonglong2 wv = *(const ulonglong2*)(W4 + dd*128 + r*4);
                const ulonglong2 qv = *(const ulonglong2*)(Q4 + dd*128 + r*4);
                const ulonglong2 s0 = *(const ulonglong2*)(S + (2*dd  )*16 + cq);
                const ulonglong2 s1 = *(const ulonglong2*)(S + (2*dd+1)*16 + cq);
                ffma2(u0, wv.x, s0.x); ffma2(u1, wv.x, s0.y);
                ffma2(u0, wv.y, s1.x); ffma2(u1, wv.y, s1.y);
                ffma2(o0, qv.x, s0.x); ffma2(o1, qv.x, s0.y);
                ffma2(o0, qv.y, s1.x); ffma2(o1, qv.y, s1.y);
            }
        }
        __syncthreads();   // bar1: S/W4/Q4/UST reads done

        // ---- prefetch chunk t+1 ----
        {
            const size_t ch = cbase + ((t+1 < NCHUNK) ? (t+1) : t);
            uint32_t sw = (uint32_t)__cvta_generic_to_shared(W4);
            uint32_t sq = (uint32_t)__cvta_generic_to_shared(Q4);
            uint32_t sk = (uint32_t)__cvta_generic_to_shared(K + nbuf*4096);
            uint32_t sa = (uint32_t)__cvta_generic_to_shared(AT + nbuf*1024);
            uint32_t su = (uint32_t)__cvta_generic_to_shared(UST + nbuf*512);
            const float4* gw = (const float4*)(g_w4 + ch*8192);
            const float4* gq = (const float4*)(g_q4 + ch*8192);
            const float4* gk = (const float4*)(g_k  + ch*4096);
            const float4* ga = (const float4*)(g_a  + ch*1024);
            for (int e = tid; e < 2048; e += 256) { cpa16(sw + e*16, gw + e); cpa16(sq + e*16, gq + e); }
            for (int e = tid; e < 1024; e += 256) cpa16(sk + e*16, gk + e);
            for (int e = tid; e < 256;  e += 256) cpa16(sa + e*16, ga + e);
            cpa8(su + tid*8, g_u + ch*4096 + (tid>>3)*DV + j0 + (tid&7)*2);
            cpa_commit();
        }

        // ---- combine #1: kh=1 partials -> kh=0 ; write UN ----
        if (kh) {
            ulonglong2 w2;
            w2.x = u0; w2.y = u1; *(ulonglong2*)(CMB + lid128*8    ) = w2;
            w2.x = o0; w2.y = o1; *(ulonglong2*)(CMB + lid128*8 + 4) = w2;
            o0 = 0ull; o1 = 0ull;
        }
        __syncthreads();   // bar2
        if (!kh) {
            ulonglong2 pu = *(const ulonglong2*)(CMB + lid128*8);
            ulonglong2 po = *(const ulonglong2*)(CMB + lid128*8 + 4);
            u0 = addf2(u0, pu.x); u1 = addf2(u1, pu.y);
            o0 = addf2(o0, po.x); o1 = addf2(o1, po.y);
            ulonglong2 w2; w2.x = u0; w2.y = u1;
            *(ulonglong2*)(UN + r*16 + cq) = w2;
        }
        __syncthreads();   // bar3: UN ready

        // ---- Pass 2a (split-T): o += att_local @ u_new ----
        {
            const int t0 = kh * 8;
            #pragma unroll 4
            for (int m = 0; m < 8; m++) {
                int tt = t0 + m;
                float2 av = *(const float2*)(ATb + r*32 + 2*tt);
                u64t ax = dupf(av.x), ay = dupf(av.y);
                const ulonglong2 n0 = *(const ulonglong2*)(UN + (2*tt  )*16 + cq);
                const ulonglong2 n1 = *(const ulonglong2*)(UN + (2*tt+1)*16 + cq);
                ffma2(o0, ax, n0.x); ffma2(o1, ax, n0.y);
                ffma2(o0, ay, n1.x); ffma2(o1, ay, n1.y);
            }
        }
        if (kh) {
            ulonglong2 w2; w2.x = o0; w2.y = o1;
            *(ulonglong2*)(CMB + lid128*4) = w2;
        }
        __syncthreads();   // bar4
        if (!kh) {
            ulonglong2 po = *(const ulonglong2*)(CMB + lid128*4);
            o0 = addf2(o0, po.x); o1 = addf2(o1, po.y);
            ulonglong2 w2; w2.x = o0; w2.y = o1;
            *(ulonglong2*)(out + ((size_t)bh*SEQ + (size_t)t*CHK + r)*DV + j0 + cq) = w2;
        }

        // ---- Pass 2b: S += k^T @ u_new (all threads) ----
        {
            ulonglong2 r0 = *(const ulonglong2*)(S + (2*dp  )*16 + c2);
            ulonglong2 r1 = *(const ulonglong2*)(S + (2*dp+1)*16 + c2);
            #pragma unroll 8
            for (int i = 0; i < CHK; i++) {
                float2 kp = *(const float2*)(Kb + i*128 + 2*dp);
                u64t kx = dupf(kp.x), ky = dupf(kp.y);
                const ulonglong2 na = *(const ulonglong2*)(UN + i*16 + c2);
                ffma2(r0.x, kx, na.x); ffma2(r0.y, kx, na.y);
                ffma2(r1.x, ky, na.x); ffma2(r1.y, ky, na.y);
            }
            *(ulonglong2*)(S + (2*dp  )*16 + c2) = r0;
            *(ulonglong2*)(S + (2*dp+1)*16 + c2) = r1;
        }

        cpa_wait0();
        __syncthreads();   // bar5: S updated + next chunk staged
    }

    if (write_state) {
        const int d = tid >> 1;
        const int c = (tid & 1) * 8;
        *(float4*)(out + (size_t)O_ELEMS + (size_t)bh*(DK*DV) + d*DV + j0 + c) =
            *(const float4*)(S + d*16 + c);
        *(float4*)(out + (size_t)O_ELEMS + (size_t)bh*(DK*DV) + d*DV + j0 + c + 4) =
            *(const float4*)(S + d*16 + c + 4);
    }
}

// ============================================================================
extern "C" void kernel_launch(void* const* d_in, const int* in_sizes, int n_in,
                              void* d_out, int out_size) {
    const float* q    = (const float*)d_in[0];
    const float* k    = (const float*)d_in[1];
    const float* v    = (const float*)d_in[2];
    const float* beta = (const float*)d_in[3];
    float* out = (float*)d_out;

    const int smem1 = P_TOT * 4;     // 96128 B
    const int smem2 = SM_TOT * 4;    // 124928 B
    cudaFuncSetAttribute(prep_kernel, cudaFuncAttributeMaxDynamicSharedMemorySize, smem1);
    cudaFuncSetAttribute(scan_kernel, cudaFuncAttributeMaxDynamicSharedMemorySize, smem2);

    const int write_state = (out_size >= O_ELEMS + S_ELEMS) ? 1 : 0;

    prep_kernel<<<TOTAL_CHUNKS, 256, smem1>>>(q, k, v, beta);
    scan_kernel<<<BHN*8, 256, smem2>>>(out, write_state);
    // 5-launch period so ncu (-s 5 -c 1) captures prep_kernel (launch #6) next round.
    noop_kernel<<<1, 1>>>();
    noop_kernel<<<1, 1>>>();
    noop_kernel<<<1, 1>>>();
}